// round 5
// baseline (speedup 1.0000x reference)
#include <cuda_runtime.h>
#include <cuda_bf16.h>
#include <cstdint>

#define N_NODES 50000
#define IN_F    64
#define HIDDEN  512
#define N_EDGES 160000
#define N_TRAIN 80000
#define N_CLASS 7
#define BN_EPS  1e-5f

// ---------------- static device scratch (no allocation) ----------------
__device__ __align__(16) float g_bufA[(size_t)N_NODES * HIDDEN];
__device__ __align__(16) float g_bufB[(size_t)N_NODES * HIDDEN];
__device__ __align__(16) float g_agg0[(size_t)N_NODES * IN_F];
__device__ __align__(16) int8_t g_qAh[(size_t)N_NODES * HIDDEN];
__device__ __align__(16) int8_t g_qAl[(size_t)N_NODES * HIDDEN];
__device__ __align__(16) int8_t g_qBh[(size_t)N_NODES * HIDDEN];
__device__ __align__(16) int8_t g_qBl[(size_t)N_NODES * HIDDEN];
__device__ __align__(16) float g_sA[N_NODES + 128];
__device__ __align__(16) float g_sB[N_NODES + 128];
#define WSLOT (HIDDEN * HIDDEN)
__device__ __align__(16) int8_t g_qWh[6 * WSLOT];
__device__ __align__(16) int8_t g_qWl[6 * WSLOT];
__device__ __align__(16) float g_sW[6 * HIDDEN];

// ---------------- PTX helpers (base-target, sm_80-class) ----------------
__device__ __forceinline__ uint32_t cvta_shared(const void* p) {
    uint32_t a;
    asm("{ .reg .u64 t; cvta.to.shared.u64 t, %1; cvt.u32.u64 %0, t; }" : "=r"(a) : "l"(p));
    return a;
}
#define CP16(dst, src) \
    asm volatile("cp.async.cg.shared.global [%0], [%1], 16;" :: "r"(dst), "l"(src))
#define CP_COMMIT() asm volatile("cp.async.commit_group;" ::: "memory")
#define CP_WAIT1()  asm volatile("cp.async.wait_group 1;" ::: "memory")

__device__ __forceinline__ void ldm4(uint32_t* r, uint32_t addr) {
    asm volatile("ldmatrix.sync.aligned.m8n8.x4.shared.b16 {%0,%1,%2,%3}, [%4];"
        : "=r"(r[0]), "=r"(r[1]), "=r"(r[2]), "=r"(r[3]) : "r"(addr));
}
__device__ __forceinline__ void imma16832(int* d, const uint32_t* a, const uint32_t* b) {
    asm volatile(
        "mma.sync.aligned.m16n8k32.row.col.s32.s8.s8.s32 "
        "{%0,%1,%2,%3},{%4,%5,%6,%7},{%8,%9},{%0,%1,%2,%3};"
        : "+r"(d[0]), "+r"(d[1]), "+r"(d[2]), "+r"(d[3])
        : "r"(a[0]), "r"(a[1]), "r"(a[2]), "r"(a[3]), "r"(b[0]), "r"(b[1]));
}
__device__ __forceinline__ uint32_t pack4(int a, int b, int c, int d) {
    return (uint32_t)(a & 0xFF) | ((uint32_t)(b & 0xFF) << 8) |
           ((uint32_t)(c & 0xFF) << 16) | ((uint32_t)(d & 0xFF) << 24);
}

// ---------------- IMMA split-int8 GEMM ----------------
// C[M,512] = sA_r*sB_c*((Ahi+Alo/254)@(Bhi+Blo/254)^T)  (lo*lo dropped)
// CTA 128x128, BK=64 (2x k32), 3-stage cp.async, 8 warps of 32x64. fp32 out.
#define GBM   128
#define GBN   128
#define GBK   64
#define ROWB  80                     // 64B data + 16B pad
#define MATB  (128 * ROWB)           // 10240
#define STB   (4 * MATB)             // 40960 (Ah,Al,Bh,Bl)
#define NSTAGE 3
#define SMEMSZ (NSTAGE * STB)        // 122880

template <bool RELU, bool BN_EN>
__global__ void __launch_bounds__(256)
imma_gemm_kernel(const int8_t* __restrict__ Ah, const int8_t* __restrict__ Al,
                 const float* __restrict__ sA,
                 const int8_t* __restrict__ Bh, const int8_t* __restrict__ Bl,
                 const float* __restrict__ sB,
                 const float* __restrict__ bias,
                 const float* __restrict__ bng, const float* __restrict__ bnb,
                 const float* __restrict__ bnm, const float* __restrict__ bnv,
                 float* __restrict__ Cf, float* __restrict__ Cf2,
                 const float* __restrict__ epsp,
                 int M, int K) {
    extern __shared__ char smem[];
    const uint32_t sbase = cvta_shared(smem);
    const int tid = threadIdx.x, lane = tid & 31, wid = tid >> 5;
    const int wm = wid >> 1, wn = wid & 1;
    const int rowBase = blockIdx.y * GBM;
    const int colBase = blockIdx.x * GBN;
    const int NC = K / GBK;

    int P1[2][8][4], P23[2][8][4];
#pragma unroll
    for (int a = 0; a < 2; a++)
#pragma unroll
        for (int b = 0; b < 8; b++)
#pragma unroll
            for (int c = 0; c < 4; c++) { P1[a][b][c] = 0; P23[a][b][c] = 0; }

    auto load_stage = [&](int c) {
        const int st = c % NSTAGE;
        const uint32_t base = sbase + st * STB;
        const int kOff = c * GBK;
#pragma unroll
        for (int u = 0; u < 2; u++) {
            int idx = tid + u * 256;
            int row = idx >> 2, ch = idx & 3;
            int gr = rowBase + row;
            if (gr > M - 1) gr = M - 1;
            size_t ga = (size_t)gr * K + kOff + ch * 16;
            uint32_t so = (uint32_t)row * ROWB + ch * 16;
            CP16(base + so, Ah + ga);
            CP16(base + MATB + so, Al + ga);
            size_t gb = (size_t)(colBase + row) * K + kOff + ch * 16;
            CP16(base + 2 * MATB + so, Bh + gb);
            CP16(base + 3 * MATB + so, Bl + gb);
        }
        CP_COMMIT();
    };

    const int mrow = (lane & 7) + ((lane >> 3) & 1) * 8;
    const uint32_t aoff = (uint32_t)(wm * 32 + mrow) * ROWB + (lane >> 4) * 16;
    const int nrow = (lane & 7) + ((lane >> 4) << 3);
    const uint32_t boff = (uint32_t)(wn * 64 + nrow) * ROWB + ((lane >> 3) & 1) * 16;

    load_stage(0);
    if (NC > 1) load_stage(1); else CP_COMMIT();

    for (int c = 0; c < NC; c++) {
        CP_WAIT1();
        __syncthreads();
        if (c + 2 < NC) load_stage(c + 2);
        else            CP_COMMIT();

        const int st = c % NSTAGE;
        const uint32_t aB = sbase + st * STB;
        const uint32_t bB = aB + 2 * MATB;
#pragma unroll
        for (int ks = 0; ks < 2; ks++) {      // two k32 steps per BK=64
            uint32_t ahf[2][4], alf[2][4], bhf[4][4], blf[4][4];
#pragma unroll
            for (int mt = 0; mt < 2; mt++) {
                uint32_t ad = aB + aoff + mt * (16 * ROWB) + ks * 32;
                ldm4(ahf[mt], ad);
                ldm4(alf[mt], ad + MATB);
            }
#pragma unroll
            for (int jp = 0; jp < 4; jp++) {
                uint32_t bd = bB + boff + jp * (16 * ROWB) + ks * 32;
                ldm4(bhf[jp], bd);
                ldm4(blf[jp], bd + MATB);
            }
#pragma unroll
            for (int mt = 0; mt < 2; mt++)
#pragma unroll
                for (int j = 0; j < 8; j++)
                    imma16832(P1[mt][j], ahf[mt], &bhf[j >> 1][(j & 1) * 2]);
#pragma unroll
            for (int mt = 0; mt < 2; mt++)
#pragma unroll
                for (int j = 0; j < 8; j++)
                    imma16832(P23[mt][j], ahf[mt], &blf[j >> 1][(j & 1) * 2]);
#pragma unroll
            for (int mt = 0; mt < 2; mt++)
#pragma unroll
                for (int j = 0; j < 8; j++)
                    imma16832(P23[mt][j], alf[mt], &bhf[j >> 1][(j & 1) * 2]);
        }
    }

    // ---------------- epilogue (fp32 out; optional scaled second copy) ------
    const int g = lane >> 2, t = lane & 3;
    const float es = Cf2 ? (1.0f + *epsp) : 0.0f;
#pragma unroll
    for (int mt = 0; mt < 2; mt++)
#pragma unroll
        for (int half = 0; half < 2; half++) {
            int r = rowBase + wm * 32 + mt * 16 + half * 8 + g;
            if (r >= M) continue;
            float sa = sA[r];
#pragma unroll
            for (int j = 0; j < 8; j++) {
                float v[2];
#pragma unroll
                for (int e = 0; e < 2; e++) {
                    int cidx = colBase + wn * 64 + j * 8 + 2 * t + e;
                    float raw = sa * sB[cidx] *
                        ((float)P1[mt][j][half * 2 + e] +
                         (float)P23[mt][j][half * 2 + e] * (1.0f / 254.0f));
                    float x = raw + bias[cidx];
                    if (RELU) x = fmaxf(x, 0.0f);
                    if (BN_EN)
                        x = (x - bnm[cidx]) * rsqrtf(bnv[cidx] + BN_EPS) * bng[cidx] + bnb[cidx];
                    v[e] = x;
                }
                int c0 = colBase + wn * 64 + j * 8 + 2 * t;
                *(float2*)(Cf + (size_t)r * HIDDEN + c0) = make_float2(v[0], v[1]);
                if (Cf2)
                    *(float2*)(Cf2 + (size_t)r * HIDDEN + c0) =
                        make_float2(v[0] * es, v[1] * es);
            }
        }
}

// ---------------- auxiliary kernels ----------------
__global__ void scale_copy_kernel(const float4* __restrict__ in, float4* __restrict__ out,
                                  const float* __restrict__ eps, int n4) {
    float s = 1.0f + *eps;
    int i = blockIdx.x * blockDim.x + threadIdx.x;
    if (i < n4) {
        float4 v = in[i];
        v.x *= s; v.y *= s; v.z *= s; v.w *= s;
        out[i] = v;
    }
}

__global__ void scatter_add_kernel(const float* __restrict__ h, float* __restrict__ out,
                                   const int* __restrict__ src, const int* __restrict__ dst,
                                   int nEdges, int F) {
    int warp = (blockIdx.x * blockDim.x + threadIdx.x) >> 5;
    int lane = threadIdx.x & 31;
    if (warp >= nEdges) return;
    int s = src[warp], d = dst[warp];
    const float4* hs = (const float4*)(h + (size_t)s * F);
    float* od = out + (size_t)d * F;
    int f4 = F >> 2;
    for (int i = lane; i < f4; i += 32) {
        float4 v = hs[i];
        atomicAdd(od + 4 * i + 0, v.x);
        atomicAdd(od + 4 * i + 1, v.y);
        atomicAdd(od + 4 * i + 2, v.z);
        atomicAdd(od + 4 * i + 3, v.w);
    }
}

// fp32[M,K] -> per-row-scaled int8 hi/lo + scale. One warp per row.
__global__ void rowquant_kernel(const float* __restrict__ X,
                                int8_t* __restrict__ qh, int8_t* __restrict__ ql,
                                float* __restrict__ s, int M, int K) {
    int warp = (blockIdx.x * blockDim.x + threadIdx.x) >> 5;
    int lane = threadIdx.x & 31;
    if (warp >= M) return;
    const float* row = X + (size_t)warp * K;
    float am = 0.0f;
    for (int k = lane * 4; k < K; k += 128) {
        float4 v = *(const float4*)(row + k);
        am = fmaxf(am, fmaxf(fmaxf(fabsf(v.x), fabsf(v.y)), fmaxf(fabsf(v.z), fabsf(v.w))));
    }
#pragma unroll
    for (int o = 16; o; o >>= 1) am = fmaxf(am, __shfl_xor_sync(0xffffffffu, am, o));
    float inv = am > 0.0f ? 127.0f / am : 0.0f;
    if (lane == 0) s[warp] = am * (1.0f / 127.0f);
    for (int base = lane * 16; base < K; base += 512) {
        uint32_t ph[4], pl[4];
#pragma unroll
        for (int q = 0; q < 4; q++) {
            float4 v = *(const float4*)(row + base + q * 4);
            float t0 = v.x * inv, t1 = v.y * inv, t2 = v.z * inv, t3 = v.w * inv;
            float h0 = rintf(t0), h1 = rintf(t1), h2 = rintf(t2), h3 = rintf(t3);
            int l0 = (int)rintf((t0 - h0) * 254.0f);
            int l1 = (int)rintf((t1 - h1) * 254.0f);
            int l2 = (int)rintf((t2 - h2) * 254.0f);
            int l3 = (int)rintf((t3 - h3) * 254.0f);
            ph[q] = pack4((int)h0, (int)h1, (int)h2, (int)h3);
            pl[q] = pack4(l0, l1, l2, l3);
        }
        *(uint4*)(qh + (size_t)warp * K + base) = make_uint4(ph[0], ph[1], ph[2], ph[3]);
        *(uint4*)(ql + (size_t)warp * K + base) = make_uint4(pl[0], pl[1], pl[2], pl[3]);
    }
}

// W[K,N] f32 -> Wt[N,K] f32 (transpose)
__global__ void wtrans_kernel(const float* __restrict__ W, float* __restrict__ Wt,
                              int K, int N) {
    __shared__ float t[32][33];
    int n0 = blockIdx.x * 32, k0 = blockIdx.y * 32;
    int tx = threadIdx.x, ty = threadIdx.y;
#pragma unroll
    for (int i = 0; i < 4; i++)
        t[ty + i * 8][tx] = W[(size_t)(k0 + ty + i * 8) * N + n0 + tx];
    __syncthreads();
#pragma unroll
    for (int i = 0; i < 4; i++)
        Wt[(size_t)(n0 + ty + i * 8) * K + k0 + tx] = t[tx][ty + i * 8];
}

__global__ void __launch_bounds__(256)
edge_pred_kernel(const float* __restrict__ h, const int* __restrict__ ei,
                 const int* __restrict__ train_id, const float* __restrict__ W,
                 const float* __restrict__ b, float* __restrict__ out) {
    __shared__ float sW[HIDDEN * N_CLASS];
    __shared__ float sb[N_CLASS];
    for (int i = threadIdx.x; i < HIDDEN * N_CLASS; i += blockDim.x) sW[i] = W[i];
    if (threadIdx.x < N_CLASS) sb[threadIdx.x] = b[threadIdx.x];
    __syncthreads();
    int warp = (blockIdx.x * blockDim.x + threadIdx.x) >> 5;
    int lane = threadIdx.x & 31;
    if (warp >= N_TRAIN) return;
    int te = train_id[warp];
    int n0 = ei[te], n1 = ei[N_EDGES + te];
    const float4* h0 = (const float4*)(h + (size_t)n0 * HIDDEN);
    const float4* h1 = (const float4*)(h + (size_t)n1 * HIDDEN);
    float acc[N_CLASS];
#pragma unroll
    for (int j = 0; j < N_CLASS; j++) acc[j] = 0.0f;
    for (int k4 = lane; k4 < HIDDEN / 4; k4 += 32) {
        float4 a = h0[k4], c = h1[k4];
        float p0 = a.x * c.x, p1 = a.y * c.y, p2 = a.z * c.z, p3 = a.w * c.w;
        int k = k4 * 4;
#pragma unroll
        for (int j = 0; j < N_CLASS; j++)
            acc[j] += p0 * sW[(k + 0) * N_CLASS + j] + p1 * sW[(k + 1) * N_CLASS + j] +
                      p2 * sW[(k + 2) * N_CLASS + j] + p3 * sW[(k + 3) * N_CLASS + j];
    }
#pragma unroll
    for (int j = 0; j < N_CLASS; j++)
#pragma unroll
        for (int off = 16; off > 0; off >>= 1)
            acc[j] += __shfl_xor_sync(0xffffffffu, acc[j], off);
    if (lane == 0) {
#pragma unroll
        for (int j = 0; j < N_CLASS; j++)
            out[(size_t)warp * N_CLASS + j] = acc[j] + sb[j];
    }
}

// ---------------- launcher ----------------
extern "C" void kernel_launch(void* const* d_in, const int* in_sizes, int n_in,
                              void* d_out, int out_size) {
    const float* x     = (const float*)d_in[0];
    const int*   ei    = (const int*)d_in[1];
    const int*   trid  = (const int*)d_in[2];
    const float* W1    = (const float*)d_in[3];
    const float* b1    = (const float*)d_in[4];
    const float* W2    = (const float*)d_in[5];
    const float* b2    = (const float*)d_in[6];
    const float* W3    = (const float*)d_in[7];
    const float* b3    = (const float*)d_in[8];
    const float* bn1g  = (const float*)d_in[9];
    const float* bn1b  = (const float*)d_in[10];
    const float* bn1m  = (const float*)d_in[11];
    const float* bn1v  = (const float*)d_in[12];
    const float* eps1  = (const float*)d_in[13];
    const float* W4    = (const float*)d_in[14];
    const float* b4    = (const float*)d_in[15];
    const float* bn2g  = (const float*)d_in[16];
    const float* bn2b  = (const float*)d_in[17];
    const float* bn2m  = (const float*)d_in[18];
    const float* bn2v  = (const float*)d_in[19];
    const float* eps2  = (const float*)d_in[20];
    const float* lin1W = (const float*)d_in[21];
    const float* lin1b = (const float*)d_in[22];
    const float* lin2W = (const float*)d_in[23];
    const float* lin2b = (const float*)d_in[24];
    const float* fc2W  = (const float*)d_in[25];
    const float* fc2b  = (const float*)d_in[26];
    float* out = (float*)d_out;

    float *bufA, *bufB, *agg0, *sA, *sB, *sW;
    int8_t *qAh, *qAl, *qBh, *qBl, *qWh, *qWl;
    cudaGetSymbolAddress((void**)&bufA, g_bufA);
    cudaGetSymbolAddress((void**)&bufB, g_bufB);
    cudaGetSymbolAddress((void**)&agg0, g_agg0);
    cudaGetSymbolAddress((void**)&qAh, g_qAh);
    cudaGetSymbolAddress((void**)&qAl, g_qAl);
    cudaGetSymbolAddress((void**)&qBh, g_qBh);
    cudaGetSymbolAddress((void**)&qBl, g_qBl);
    cudaGetSymbolAddress((void**)&sA, g_sA);
    cudaGetSymbolAddress((void**)&sB, g_sB);
    cudaGetSymbolAddress((void**)&qWh, g_qWh);
    cudaGetSymbolAddress((void**)&qWl, g_qWl);
    cudaGetSymbolAddress((void**)&sW, g_sW);

    cudaFuncSetAttribute(imma_gemm_kernel<true, false>,
                         cudaFuncAttributeMaxDynamicSharedMemorySize, SMEMSZ);
    cudaFuncSetAttribute(imma_gemm_kernel<true, true>,
                         cudaFuncAttributeMaxDynamicSharedMemorySize, SMEMSZ);
    cudaFuncSetAttribute(imma_gemm_kernel<false, false>,
                         cudaFuncAttributeMaxDynamicSharedMemorySize, SMEMSZ);

    const int* src = ei;
    const int* dst = ei + N_EDGES;
    dim3 wb(32, 8);

    // weight prep: transpose (scratch = bufB) + row-quant
    const float* Ws[6] = {W1, W2, W3, W4, lin1W, lin2W};
    const int    Ks[6] = {IN_F, HIDDEN, HIDDEN, HIDDEN, HIDDEN, HIDDEN};
    for (int i = 0; i < 6; i++) {
        wtrans_kernel<<<dim3(16, Ks[i] / 32), wb>>>(Ws[i], bufB, Ks[i], HIDDEN);
        rowquant_kernel<<<(HIDDEN * 32 + 255) / 256, 256>>>(
            bufB, qWh + (size_t)i * WSLOT, qWl + (size_t)i * WSLOT, sW + i * HIDDEN,
            HIDDEN, Ks[i]);
    }

    // agg1 on x (fp32) then quantize
    {
        int n4 = N_NODES * IN_F / 4;
        scale_copy_kernel<<<(n4 + 255) / 256, 256>>>((const float4*)x, (float4*)agg0, eps1, n4);
        scatter_add_kernel<<<(N_EDGES * 32 + 255) / 256, 256>>>(x, agg0, src, dst, N_EDGES, IN_F);
        rowquant_kernel<<<(N_NODES * 32 + 255) / 256, 256>>>(agg0, qAh, qAl, sA, N_NODES, IN_F);
    }

    dim3 gg(HIDDEN / GBN, (N_NODES + GBM - 1) / GBM);  // (4, 391)
    int qblocks = (N_NODES * 32 + 255) / 256;

    // L1: relu(agg @ W1 + b1) -> fp32 bufA -> q8 (qB, sB)
    imma_gemm_kernel<true, false><<<gg, 256, SMEMSZ>>>(
        qAh, qAl, sA, qWh + 0 * WSLOT, qWl + 0 * WSLOT, sW + 0 * HIDDEN, b1,
        nullptr, nullptr, nullptr, nullptr, bufA, nullptr, nullptr, N_NODES, IN_F);
    rowquant_kernel<<<qblocks, 256>>>(bufA, qBh, qBl, sB, N_NODES, HIDDEN);
    // L2: relu(h @ W2 + b2) -> fp32 bufA -> q8 (qA, sA)
    imma_gemm_kernel<true, false><<<gg, 256, SMEMSZ>>>(
        qBh, qBl, sB, qWh + 1 * WSLOT, qWl + 1 * WSLOT, sW + 1 * HIDDEN, b2,
        nullptr, nullptr, nullptr, nullptr, bufA, nullptr, nullptr, N_NODES, HIDDEN);
    rowquant_kernel<<<qblocks, 256>>>(bufA, qAh, qAl, sA, N_NODES, HIDDEN);
    // L3: bn1(relu(h @ W3 + b3)) -> fp32 bufA + (1+eps2)-scaled bufB
    imma_gemm_kernel<true, true><<<gg, 256, SMEMSZ>>>(
        qAh, qAl, sA, qWh + 2 * WSLOT, qWl + 2 * WSLOT, sW + 2 * HIDDEN, b3,
        bn1g, bn1b, bn1m, bn1v, bufA, bufB, eps2, N_NODES, HIDDEN);
    // agg2: bufB += bufA[src] scattered, then quantize
    scatter_add_kernel<<<(N_EDGES * 32 + 255) / 256, 256>>>(bufA, bufB, src, dst, N_EDGES, HIDDEN);
    rowquant_kernel<<<qblocks, 256>>>(bufB, qAh, qAl, sA, N_NODES, HIDDEN);
    // L4: bn2(relu(h @ W4 + b4)) -> fp32 bufA -> q8 (qB, sB)
    imma_gemm_kernel<true, true><<<gg, 256, SMEMSZ>>>(
        qAh, qAl, sA, qWh + 3 * WSLOT, qWl + 3 * WSLOT, sW + 3 * HIDDEN, b4,
        bn2g, bn2b, bn2m, bn2v, bufA, nullptr, nullptr, N_NODES, HIDDEN);
    rowquant_kernel<<<qblocks, 256>>>(bufA, qBh, qBl, sB, N_NODES, HIDDEN);
    // L5: relu(h @ lin1W + lin1b) -> fp32 bufA -> q8 (qA, sA)
    imma_gemm_kernel<true, false><<<gg, 256, SMEMSZ>>>(
        qBh, qBl, sB, qWh + 4 * WSLOT, qWl + 4 * WSLOT, sW + 4 * HIDDEN, lin1b,
        nullptr, nullptr, nullptr, nullptr, bufA, nullptr, nullptr, N_NODES, HIDDEN);
    rowquant_kernel<<<qblocks, 256>>>(bufA, qAh, qAl, sA, N_NODES, HIDDEN);
    // L6: h @ lin2W + lin2b -> fp32 bufA
    imma_gemm_kernel<false, false><<<gg, 256, SMEMSZ>>>(
        qAh, qAl, sA, qWh + 5 * WSLOT, qWl + 5 * WSLOT, sW + 5 * HIDDEN, lin2b,
        nullptr, nullptr, nullptr, nullptr, bufA, nullptr, nullptr, N_NODES, HIDDEN);
    // edge classifier
    edge_pred_kernel<<<(N_TRAIN * 32 + 255) / 256, 256>>>(bufA, ei, trid, fc2W, fc2b, out);
}

// round 6
// speedup vs baseline: 3.6698x; 3.6698x over previous
#include <cuda_runtime.h>
#include <cuda_bf16.h>
#include <cstdint>

#define N_NODES 50000
#define IN_F    64
#define HIDDEN  512
#define N_EDGES 160000
#define N_TRAIN 80000
#define N_CLASS 7
#define BN_EPS  1e-5f

// ---------------- static device scratch (no allocation) ----------------
__device__ __align__(16) float g_bufA[(size_t)N_NODES * HIDDEN];
__device__ __align__(16) float g_bufB[(size_t)N_NODES * HIDDEN];
__device__ __align__(16) float g_agg0[(size_t)N_NODES * IN_F];
__device__ __align__(16) __nv_bfloat16 g_hA[(size_t)N_NODES * HIDDEN];
__device__ __align__(16) __nv_bfloat16 g_lA[(size_t)N_NODES * HIDDEN];
__device__ __align__(16) __nv_bfloat16 g_hB[(size_t)N_NODES * HIDDEN];
__device__ __align__(16) __nv_bfloat16 g_lB[(size_t)N_NODES * HIDDEN];
#define WSLOT (HIDDEN * HIDDEN)
__device__ __align__(16) __nv_bfloat16 g_wh[6 * WSLOT];
__device__ __align__(16) __nv_bfloat16 g_wl[6 * WSLOT];

// ---------------- PTX helpers (base-target only: sm_80-class) ----------------
__device__ __forceinline__ uint32_t cvta_shared(const void* p) {
    uint32_t a;
    asm("{ .reg .u64 t; cvta.to.shared.u64 t, %1; cvt.u32.u64 %0, t; }" : "=r"(a) : "l"(p));
    return a;
}
#define CP16(dst, src) \
    asm volatile("cp.async.cg.shared.global [%0], [%1], 16;" :: "r"(dst), "l"(src))
#define CP_COMMIT() asm volatile("cp.async.commit_group;" ::: "memory")
#define CP_WAIT1()  asm volatile("cp.async.wait_group 1;" ::: "memory")

__device__ __forceinline__ void ldm4(uint32_t* r, uint32_t addr) {
    asm volatile("ldmatrix.sync.aligned.m8n8.x4.shared.b16 {%0,%1,%2,%3}, [%4];"
        : "=r"(r[0]), "=r"(r[1]), "=r"(r[2]), "=r"(r[3]) : "r"(addr));
}
__device__ __forceinline__ void mma16816(float* d, const uint32_t* a, const uint32_t* b) {
    asm volatile(
        "mma.sync.aligned.m16n8k16.row.col.f32.bf16.bf16.f32 "
        "{%0,%1,%2,%3},{%4,%5,%6,%7},{%8,%9},{%0,%1,%2,%3};"
        : "+f"(d[0]), "+f"(d[1]), "+f"(d[2]), "+f"(d[3])
        : "r"(a[0]), "r"(a[1]), "r"(a[2]), "r"(a[3]), "r"(b[0]), "r"(b[1]));
}

// ---------------- HMMA split-bf16 GEMM ----------------
// C[M,512] = A[M,K] @ B[512,K]^T with A=(Ah+Al), B=(Bh+Bl) bf16.
// CTA 128x128, BK=32, 2-stage cp.async (2 CTAs/SM), 8 warps of 32x64.
#define GBM   128
#define GBN   128
#define GBK   32
#define ROWB  80                     // 64B data + 16B pad (conflict-free ldmatrix)
#define MATB  (128 * ROWB)           // 10240 per matrix per stage
#define STB   (4 * MATB)             // 40960 per stage (Ah,Al,Bh,Bl)
#define NSTAGE 2
#define SMEMSZ (NSTAGE * STB)        // 81920 -> 2 CTAs/SM

template <bool RELU, bool BN_EN, bool OUTF32>
__global__ void __launch_bounds__(256, 2)
hmma_gemm_kernel(const __nv_bfloat16* __restrict__ Ah, const __nv_bfloat16* __restrict__ Al,
                 const __nv_bfloat16* __restrict__ Bh, const __nv_bfloat16* __restrict__ Bl,
                 const float* __restrict__ bias,
                 const float* __restrict__ bng, const float* __restrict__ bnb,
                 const float* __restrict__ bnm, const float* __restrict__ bnv,
                 float* __restrict__ Cf, float* __restrict__ Cf2,
                 const float* __restrict__ epsp,
                 __nv_bfloat16* __restrict__ Ch, __nv_bfloat16* __restrict__ Cl,
                 int M, int K) {
    extern __shared__ char smem[];
    const uint32_t sb = cvta_shared(smem);
    const int tid = threadIdx.x, lane = tid & 31, wid = tid >> 5;
    const int wm = wid >> 1, wn = wid & 1;           // 4x2 warp grid
    const int rowBase = blockIdx.y * GBM;
    const int colBase = blockIdx.x * GBN;
    const int NC = K / GBK;

    float acc[2][8][4];
#pragma unroll
    for (int a = 0; a < 2; a++)
#pragma unroll
        for (int b = 0; b < 8; b++)
#pragma unroll
            for (int c = 0; c < 4; c++) acc[a][b][c] = 0.0f;

    auto load_stage = [&](int c) {
        const int st = c % NSTAGE;
        const uint32_t base = sb + st * STB;
        const int kOff = c * GBK;
#pragma unroll
        for (int u = 0; u < 2; u++) {
            int idx = tid + u * 256;
            int row = idx >> 2, ch = idx & 3;
            int gr = rowBase + row;
            if (gr > M - 1) gr = M - 1;              // clamp (finite junk, rows not stored)
            size_t ga = (size_t)gr * K + kOff + ch * 8;
            uint32_t so = (uint32_t)row * ROWB + ch * 16;
            CP16(base + so, Ah + ga);
            CP16(base + MATB + so, Al + ga);
            size_t gb = (size_t)(colBase + row) * K + kOff + ch * 8;
            CP16(base + 2 * MATB + so, Bh + gb);
            CP16(base + 3 * MATB + so, Bl + gb);
        }
        CP_COMMIT();
    };

    // ldmatrix per-lane address offsets
    const int mrow = (lane & 7) + ((lane >> 3) & 1) * 8;
    const uint32_t aoff = (uint32_t)(wm * 32 + mrow) * ROWB + (lane >> 4) * 16;
    const int nrow = (lane & 7) + ((lane >> 4) << 3);
    const uint32_t boff = (uint32_t)(wn * 64 + nrow) * ROWB + ((lane >> 3) & 1) * 16;

    load_stage(0);

    for (int c = 0; c < NC; c++) {
        if (c + 1 < NC) load_stage(c + 1);
        else            CP_COMMIT();          // keep group count uniform
        CP_WAIT1();                           // stage c complete
        __syncthreads();

        const int st = c % NSTAGE;
        const uint32_t aB = sb + st * STB;
        const uint32_t bB = aB + 2 * MATB;
#pragma unroll
        for (int ks = 0; ks < 2; ks++) {      // two k16 steps per BK=32
            uint32_t ahf[2][4], alf[2][4], bhf[4][4], blf[4][4];
#pragma unroll
            for (int mt = 0; mt < 2; mt++) {
                uint32_t ad = aB + aoff + mt * (16 * ROWB) + ks * 32;
                ldm4(ahf[mt], ad);
                ldm4(alf[mt], ad + MATB);
            }
#pragma unroll
            for (int jp = 0; jp < 4; jp++) {
                uint32_t bd = bB + boff + jp * (16 * ROWB) + ks * 32;
                ldm4(bhf[jp], bd);
                ldm4(blf[jp], bd + MATB);
            }
#pragma unroll
            for (int mt = 0; mt < 2; mt++)
#pragma unroll
                for (int j = 0; j < 8; j++)
                    mma16816(acc[mt][j], ahf[mt], &bhf[j >> 1][(j & 1) * 2]);
#pragma unroll
            for (int mt = 0; mt < 2; mt++)
#pragma unroll
                for (int j = 0; j < 8; j++)
                    mma16816(acc[mt][j], ahf[mt], &blf[j >> 1][(j & 1) * 2]);
#pragma unroll
            for (int mt = 0; mt < 2; mt++)
#pragma unroll
                for (int j = 0; j < 8; j++)
                    mma16816(acc[mt][j], alf[mt], &bhf[j >> 1][(j & 1) * 2]);
        }
        __syncthreads();                      // stage c free before it is overwritten
    }

    // ---------------- epilogue (direct from registers) ----------------
    const int g = lane >> 2, t = lane & 3;
    const float es = (OUTF32 && Cf2) ? (1.0f + *epsp) : 0.0f;
#pragma unroll
    for (int mt = 0; mt < 2; mt++) {
        int rbase = rowBase + wm * 32 + mt * 16 + g;
#pragma unroll
        for (int half = 0; half < 2; half++) {
            int r = rbase + half * 8;
            if (r >= M) continue;
#pragma unroll
            for (int j = 0; j < 8; j++) {
                int cidx = colBase + wn * 64 + j * 8 + 2 * t;
                float v0 = acc[mt][j][half * 2 + 0] + bias[cidx];
                float v1 = acc[mt][j][half * 2 + 1] + bias[cidx + 1];
                if (RELU) { v0 = fmaxf(v0, 0.0f); v1 = fmaxf(v1, 0.0f); }
                if (BN_EN) {
                    v0 = (v0 - bnm[cidx]) * rsqrtf(bnv[cidx] + BN_EPS) * bng[cidx] + bnb[cidx];
                    v1 = (v1 - bnm[cidx + 1]) * rsqrtf(bnv[cidx + 1] + BN_EPS) * bng[cidx + 1] + bnb[cidx + 1];
                }
                if (OUTF32) {
                    *(float2*)(Cf + (size_t)r * HIDDEN + cidx) = make_float2(v0, v1);
                    if (Cf2)
                        *(float2*)(Cf2 + (size_t)r * HIDDEN + cidx) =
                            make_float2(v0 * es, v1 * es);
                } else {
                    __nv_bfloat16 h0 = __float2bfloat16(v0);
                    __nv_bfloat16 h1 = __float2bfloat16(v1);
                    __nv_bfloat16 l0 = __float2bfloat16(v0 - __bfloat162float(h0));
                    __nv_bfloat16 l1 = __float2bfloat16(v1 - __bfloat162float(h1));
                    *(uint32_t*)(Ch + (size_t)r * HIDDEN + cidx) =
                        (uint32_t)__bfloat16_as_ushort(h0) | ((uint32_t)__bfloat16_as_ushort(h1) << 16);
                    *(uint32_t*)(Cl + (size_t)r * HIDDEN + cidx) =
                        (uint32_t)__bfloat16_as_ushort(l0) | ((uint32_t)__bfloat16_as_ushort(l1) << 16);
                }
            }
        }
    }
}

// ---------------- auxiliary kernels ----------------
__global__ void scale_copy_kernel(const float4* __restrict__ in, float4* __restrict__ out,
                                  const float* __restrict__ eps, int n4) {
    float s = 1.0f + *eps;
    int i = blockIdx.x * blockDim.x + threadIdx.x;
    if (i < n4) {
        float4 v = in[i];
        v.x *= s; v.y *= s; v.z *= s; v.w *= s;
        out[i] = v;
    }
}

__global__ void scatter_add_kernel(const float* __restrict__ h, float* __restrict__ out,
                                   const int* __restrict__ src, const int* __restrict__ dst,
                                   int nEdges, int F) {
    int warp = (blockIdx.x * blockDim.x + threadIdx.x) >> 5;
    int lane = threadIdx.x & 31;
    if (warp >= nEdges) return;
    int s = src[warp], d = dst[warp];
    const float4* hs = (const float4*)(h + (size_t)s * F);
    float* od = out + (size_t)d * F;
    int f4 = F >> 2;
    for (int i = lane; i < f4; i += 32) {
        float4 v = hs[i];
        atomicAdd(od + 4 * i + 0, v.x);
        atomicAdd(od + 4 * i + 1, v.y);
        atomicAdd(od + 4 * i + 2, v.z);
        atomicAdd(od + 4 * i + 3, v.w);
    }
}

__global__ void split_kernel(const float4* __restrict__ in, uint32_t* __restrict__ hi,
                             uint32_t* __restrict__ lo, int n4) {
    int i = blockIdx.x * blockDim.x + threadIdx.x;
    if (i >= n4) return;
    float4 v = in[i];
    __nv_bfloat16 h0 = __float2bfloat16(v.x), h1 = __float2bfloat16(v.y);
    __nv_bfloat16 h2 = __float2bfloat16(v.z), h3 = __float2bfloat16(v.w);
    __nv_bfloat16 l0 = __float2bfloat16(v.x - __bfloat162float(h0));
    __nv_bfloat16 l1 = __float2bfloat16(v.y - __bfloat162float(h1));
    __nv_bfloat16 l2 = __float2bfloat16(v.z - __bfloat162float(h2));
    __nv_bfloat16 l3 = __float2bfloat16(v.w - __bfloat162float(h3));
    hi[2 * i]     = (uint32_t)__bfloat16_as_ushort(h0) | ((uint32_t)__bfloat16_as_ushort(h1) << 16);
    hi[2 * i + 1] = (uint32_t)__bfloat16_as_ushort(h2) | ((uint32_t)__bfloat16_as_ushort(h3) << 16);
    lo[2 * i]     = (uint32_t)__bfloat16_as_ushort(l0) | ((uint32_t)__bfloat16_as_ushort(l1) << 16);
    lo[2 * i + 1] = (uint32_t)__bfloat16_as_ushort(l2) | ((uint32_t)__bfloat16_as_ushort(l3) << 16);
}

// W[K,N] f32 -> Wh[N,K], Wl[N,K] bf16 (transpose + split)
__global__ void wsplit_kernel(const float* __restrict__ W, __nv_bfloat16* __restrict__ Wh,
                              __nv_bfloat16* __restrict__ Wl, int K, int N) {
    __shared__ float t[32][33];
    int n0 = blockIdx.x * 32, k0 = blockIdx.y * 32;
    int tx = threadIdx.x, ty = threadIdx.y;
#pragma unroll
    for (int i = 0; i < 4; i++)
        t[ty + i * 8][tx] = W[(size_t)(k0 + ty + i * 8) * N + n0 + tx];
    __syncthreads();
#pragma unroll
    for (int i = 0; i < 4; i++) {
        float v = t[tx][ty + i * 8];
        __nv_bfloat16 h = __float2bfloat16(v);
        __nv_bfloat16 l = __float2bfloat16(v - __bfloat162float(h));
        size_t o = (size_t)(n0 + ty + i * 8) * K + k0 + tx;
        Wh[o] = h;
        Wl[o] = l;
    }
}

__global__ void __launch_bounds__(256)
edge_pred_kernel(const float* __restrict__ h, const int* __restrict__ ei,
                 const int* __restrict__ train_id, const float* __restrict__ W,
                 const float* __restrict__ b, float* __restrict__ out) {
    __shared__ float sW[HIDDEN * N_CLASS];
    __shared__ float sb[N_CLASS];
    for (int i = threadIdx.x; i < HIDDEN * N_CLASS; i += blockDim.x) sW[i] = W[i];
    if (threadIdx.x < N_CLASS) sb[threadIdx.x] = b[threadIdx.x];
    __syncthreads();
    int warp = (blockIdx.x * blockDim.x + threadIdx.x) >> 5;
    int lane = threadIdx.x & 31;
    if (warp >= N_TRAIN) return;
    int te = train_id[warp];
    int n0 = ei[te], n1 = ei[N_EDGES + te];
    const float4* h0 = (const float4*)(h + (size_t)n0 * HIDDEN);
    const float4* h1 = (const float4*)(h + (size_t)n1 * HIDDEN);
    float acc[N_CLASS];
#pragma unroll
    for (int j = 0; j < N_CLASS; j++) acc[j] = 0.0f;
    for (int k4 = lane; k4 < HIDDEN / 4; k4 += 32) {
        float4 a = h0[k4], c = h1[k4];
        float p0 = a.x * c.x, p1 = a.y * c.y, p2 = a.z * c.z, p3 = a.w * c.w;
        int k = k4 * 4;
#pragma unroll
        for (int j = 0; j < N_CLASS; j++)
            acc[j] += p0 * sW[(k + 0) * N_CLASS + j] + p1 * sW[(k + 1) * N_CLASS + j] +
                      p2 * sW[(k + 2) * N_CLASS + j] + p3 * sW[(k + 3) * N_CLASS + j];
    }
#pragma unroll
    for (int j = 0; j < N_CLASS; j++)
#pragma unroll
        for (int off = 16; off > 0; off >>= 1)
            acc[j] += __shfl_xor_sync(0xffffffffu, acc[j], off);
    if (lane == 0) {
#pragma unroll
        for (int j = 0; j < N_CLASS; j++)
            out[(size_t)warp * N_CLASS + j] = acc[j] + sb[j];
    }
}

// ---------------- launcher ----------------
extern "C" void kernel_launch(void* const* d_in, const int* in_sizes, int n_in,
                              void* d_out, int out_size) {
    const float* x     = (const float*)d_in[0];
    const int*   ei    = (const int*)d_in[1];
    const int*   trid  = (const int*)d_in[2];
    const float* W1    = (const float*)d_in[3];
    const float* b1    = (const float*)d_in[4];
    const float* W2    = (const float*)d_in[5];
    const float* b2    = (const float*)d_in[6];
    const float* W3    = (const float*)d_in[7];
    const float* b3    = (const float*)d_in[8];
    const float* bn1g  = (const float*)d_in[9];
    const float* bn1b  = (const float*)d_in[10];
    const float* bn1m  = (const float*)d_in[11];
    const float* bn1v  = (const float*)d_in[12];
    const float* eps1  = (const float*)d_in[13];
    const float* W4    = (const float*)d_in[14];
    const float* b4    = (const float*)d_in[15];
    const float* bn2g  = (const float*)d_in[16];
    const float* bn2b  = (const float*)d_in[17];
    const float* bn2m  = (const float*)d_in[18];
    const float* bn2v  = (const float*)d_in[19];
    const float* eps2  = (const float*)d_in[20];
    const float* lin1W = (const float*)d_in[21];
    const float* lin1b = (const float*)d_in[22];
    const float* lin2W = (const float*)d_in[23];
    const float* lin2b = (const float*)d_in[24];
    const float* fc2W  = (const float*)d_in[25];
    const float* fc2b  = (const float*)d_in[26];
    float* out = (float*)d_out;

    float *bufA, *bufB, *agg0;
    __nv_bfloat16 *hA, *lA, *hB, *lB, *wh, *wl;
    cudaGetSymbolAddress((void**)&bufA, g_bufA);
    cudaGetSymbolAddress((void**)&bufB, g_bufB);
    cudaGetSymbolAddress((void**)&agg0, g_agg0);
    cudaGetSymbolAddress((void**)&hA, g_hA);
    cudaGetSymbolAddress((void**)&lA, g_lA);
    cudaGetSymbolAddress((void**)&hB, g_hB);
    cudaGetSymbolAddress((void**)&lB, g_lB);
    cudaGetSymbolAddress((void**)&wh, g_wh);
    cudaGetSymbolAddress((void**)&wl, g_wl);

    cudaFuncSetAttribute(hmma_gemm_kernel<true, false, false>,
                         cudaFuncAttributeMaxDynamicSharedMemorySize, SMEMSZ);
    cudaFuncSetAttribute(hmma_gemm_kernel<true, true, true>,
                         cudaFuncAttributeMaxDynamicSharedMemorySize, SMEMSZ);
    cudaFuncSetAttribute(hmma_gemm_kernel<true, true, false>,
                         cudaFuncAttributeMaxDynamicSharedMemorySize, SMEMSZ);
    cudaFuncSetAttribute(hmma_gemm_kernel<false, false, true>,
                         cudaFuncAttributeMaxDynamicSharedMemorySize, SMEMSZ);

    const int* src = ei;
    const int* dst = ei + N_EDGES;

    // weight transpose + split
    dim3 wb(32, 8);
    wsplit_kernel<<<dim3(16, 2), wb>>>(W1, wh + 0 * WSLOT, wl + 0 * WSLOT, IN_F, HIDDEN);
    wsplit_kernel<<<dim3(16, 16), wb>>>(W2, wh + 1 * WSLOT, wl + 1 * WSLOT, HIDDEN, HIDDEN);
    wsplit_kernel<<<dim3(16, 16), wb>>>(W3, wh + 2 * WSLOT, wl + 2 * WSLOT, HIDDEN, HIDDEN);
    wsplit_kernel<<<dim3(16, 16), wb>>>(W4, wh + 3 * WSLOT, wl + 3 * WSLOT, HIDDEN, HIDDEN);
    wsplit_kernel<<<dim3(16, 16), wb>>>(lin1W, wh + 4 * WSLOT, wl + 4 * WSLOT, HIDDEN, HIDDEN);
    wsplit_kernel<<<dim3(16, 16), wb>>>(lin2W, wh + 5 * WSLOT, wl + 5 * WSLOT, HIDDEN, HIDDEN);

    // agg1 on x (fp32) then split
    {
        int n4 = N_NODES * IN_F / 4;
        scale_copy_kernel<<<(n4 + 255) / 256, 256>>>((const float4*)x, (float4*)agg0, eps1, n4);
        scatter_add_kernel<<<(N_EDGES * 32 + 255) / 256, 256>>>(x, agg0, src, dst, N_EDGES, IN_F);
        split_kernel<<<(n4 + 255) / 256, 256>>>((const float4*)agg0, (uint32_t*)hA, (uint32_t*)lA, n4);
    }

    dim3 gg(HIDDEN / GBN, (N_NODES + GBM - 1) / GBM);  // (4, 391)

    // L1: relu(agg @ W1 + b1) -> split pair
    hmma_gemm_kernel<true, false, false><<<gg, 256, SMEMSZ>>>(
        hA, lA, wh + 0 * WSLOT, wl + 0 * WSLOT, b1, nullptr, nullptr, nullptr, nullptr,
        nullptr, nullptr, nullptr, hB, lB, N_NODES, IN_F);
    // L2: relu(h @ W2 + b2) -> split pair
    hmma_gemm_kernel<true, false, false><<<gg, 256, SMEMSZ>>>(
        hB, lB, wh + 1 * WSLOT, wl + 1 * WSLOT, b2, nullptr, nullptr, nullptr, nullptr,
        nullptr, nullptr, nullptr, hA, lA, N_NODES, HIDDEN);
    // L3: bn1(relu(h @ W3 + b3)) -> fp32 bufA + (1+eps2)-scaled bufB (fused)
    hmma_gemm_kernel<true, true, true><<<gg, 256, SMEMSZ>>>(
        hA, lA, wh + 2 * WSLOT, wl + 2 * WSLOT, b3, bn1g, bn1b, bn1m, bn1v,
        bufA, bufB, eps2, nullptr, nullptr, N_NODES, HIDDEN);
    // agg2: bufB += bufA[src] scattered, then split
    {
        int n4 = N_NODES * HIDDEN / 4;
        scatter_add_kernel<<<(N_EDGES * 32 + 255) / 256, 256>>>(bufA, bufB, src, dst, N_EDGES, HIDDEN);
        split_kernel<<<(n4 + 255) / 256, 256>>>((const float4*)bufB, (uint32_t*)hA, (uint32_t*)lA, n4);
    }
    // L4: bn2(relu(h @ W4 + b4)) -> split pair
    hmma_gemm_kernel<true, true, false><<<gg, 256, SMEMSZ>>>(
        hA, lA, wh + 3 * WSLOT, wl + 3 * WSLOT, b4, bn2g, bn2b, bn2m, bn2v,
        nullptr, nullptr, nullptr, hB, lB, N_NODES, HIDDEN);
    // L5: relu(h @ lin1W + lin1b) -> split pair
    hmma_gemm_kernel<true, false, false><<<gg, 256, SMEMSZ>>>(
        hB, lB, wh + 4 * WSLOT, wl + 4 * WSLOT, lin1b, nullptr, nullptr, nullptr, nullptr,
        nullptr, nullptr, nullptr, hA, lA, N_NODES, HIDDEN);
    // L6: h @ lin2W + lin2b -> fp32
    hmma_gemm_kernel<false, false, true><<<gg, 256, SMEMSZ>>>(
        hA, lA, wh + 5 * WSLOT, wl + 5 * WSLOT, lin2b, nullptr, nullptr, nullptr, nullptr,
        bufA, nullptr, nullptr, nullptr, nullptr, N_NODES, HIDDEN);
    // edge classifier
    edge_pred_kernel<<<(N_TRAIN * 32 + 255) / 256, 256>>>(bufA, ei, trid, fc2W, fc2b, out);
}